// round 5
// baseline (speedup 1.0000x reference)
#include <cuda_runtime.h>
#include <cstdint>

// ---------------- problem constants ----------------
#define T_SEQ 512
#define B_SZ  256
#define IN_D  64
#define H_D   128
#define G4    512   // 4*H
#define L_N   5

// ping-pong inter-layer activation buffers (scratch via __device__ globals)
__device__ float g_bufA[T_SEQ * B_SZ * H_D];
__device__ float g_bufB[T_SEQ * B_SZ * H_D];

// ---------------- f32x2 packed FMA helpers ----------------
__device__ __forceinline__ void fma2(unsigned long long &acc,
                                     unsigned long long a,
                                     unsigned long long b) {
    asm("fma.rn.f32x2 %0, %1, %2, %3;" : "=l"(acc) : "l"(a), "l"(b), "l"(acc));
}
__device__ __forceinline__ unsigned long long pack2(float lo, float hi) {
    unsigned long long r;
    asm("mov.b64 %0, {%1, %2};" : "=l"(r) : "f"(lo), "f"(hi));
    return r;
}
__device__ __forceinline__ float sum2(unsigned long long v) {
    float lo, hi;
    asm("mov.b64 {%0, %1}, %2;" : "=f"(lo), "=f"(hi) : "l"(v));
    return lo + hi;
}
__device__ __forceinline__ float fsig(float x) {
    return __fdividef(1.0f, 1.0f + __expf(-x));
}
__device__ __forceinline__ float ftanh(float x) {
    return __fdividef(2.0f, 1.0f + __expf(-2.0f * x)) - 1.0f;
}

// One dot pass: 4 batch rows x 2 gate rows x (4*NV) k-values.
// p points at this thread's k-slice of batch row 0; row stride RS floats.
// Each LDS.128 (broadcast, conflict-free) feeds 4 fma2 (2 rows x 2 pairs).
template<int NV, int RS>
__device__ __forceinline__ void dot_pass(unsigned long long* a0,
                                         unsigned long long* a1,
                                         const float* __restrict__ p,
                                         const unsigned long long* W0,
                                         const unsigned long long* W1) {
#pragma unroll
    for (int kk = 0; kk < NV; kk++) {
#pragma unroll
        for (int b = 0; b < 4; b++) {
            ulonglong2 v = *(const ulonglong2*)(p + b * RS + 4 * kk);
            fma2(a0[b], v.x, W0[2 * kk]);
            fma2(a0[b], v.y, W0[2 * kk + 1]);
            fma2(a1[b], v.x, W1[2 * kk]);
            fma2(a1[b], v.y, W1[2 * kk + 1]);
        }
    }
}

// Full slab: 8 batch rows, write partials for 2 gate rows into g0.
template<int NV, int RS>
__device__ __forceinline__ void slab(float* __restrict__ g0,
                                     const float* __restrict__ base,
                                     const unsigned long long* W0,
                                     const unsigned long long* W1,
                                     int r0, int r1) {
    unsigned long long a0[4] = {0, 0, 0, 0}, a1[4] = {0, 0, 0, 0};
    dot_pass<NV, RS>(a0, a1, base, W0, W1);
#pragma unroll
    for (int b = 0; b < 4; b++) {
        g0[b * 128 + r0] = sum2(a0[b]);
        g0[b * 128 + r1] = sum2(a1[b]);
    }
#pragma unroll
    for (int b = 0; b < 4; b++) a0[b] = a1[b] = 0ull;
    dot_pass<NV, RS>(a0, a1, base + 4 * RS, W0, W1);
#pragma unroll
    for (int b = 0; b < 4; b++) {
        g0[(b + 4) * 128 + r0] = sum2(a0[b]);
        g0[(b + 4) * 128 + r1] = sum2(a1[b]);
    }
}

// ============================================================================
// Persistent LSTM layer. Grid 128 CTAs, cluster of 4; cluster owns 8 batch
// rows, CTA rank r owns hidden slice [32r, 32r+32) of all 4 gates.
// 512 threads = 16 warps:
//   warps 0-7  (x-group): x-part dots for step t+1, issued BEFORE the cluster
//                         wait -> they bridge the arrive->wait gap and hide
//                         the barrier latency. Then they run the epilogue.
//   warps 8-15 (h-group): LDG-prefetch x(t+2) before the wait; h-part dots
//                         for step t after it; then stage x(t+2) to smem.
// Each thread covers 2 gate rows sharing one k-slice -> every broadcast
// LDS.128 feeds 4 fma2.
// ============================================================================
template<int KIN>
__global__ void __launch_bounds__(512, 1) __cluster_dims__(4, 1, 1)
lstm_layer(const float* __restrict__ in,   // [T, B, KIN]
           float* __restrict__ out,        // [T, B, H]
           const float* __restrict__ Wih,  // [4H, KIN]
           const float* __restrict__ Whh,  // [4H, H]
           const float* __restrict__ bih,  // [4H]
           const float* __restrict__ bhh)  // [4H]
{
    constexpr int XSL = KIN / 4;       // x slice length (16 or 32)
    constexpr int NVX = XSL / 4;       // 16B chunks per x slice (4 or 8)

    extern __shared__ float sm[];
    float* gbuf = sm;                                  // [2][8][8][128]
    float* xs   = sm + 2 * 8 * 8 * 128;                // [2][8][KIN]
    float* hs   = xs + 2 * 8 * KIN;                    // [2][8][128]

    const int tid  = threadIdx.x;
    const int lane = tid & 31;
    const int w    = tid >> 5;
    const bool isx = (w < 8);
    const int rg   = w & 1;
    const int r0   = rg * 64 + lane;     // local gate rows r0, r0+32
    const int r1   = r0 + 32;

    uint32_t rank;
    asm("mov.u32 %0, %%cluster_ctarank;" : "=r"(rank));
    const int b0 = (blockIdx.x >> 2) * 8;

    const int k0 = isx ? (w >> 1) * XSL : ((w - 8) >> 1) * 32;
    const int sl = isx ? (w >> 1)       : 4 + ((w - 8) >> 1);

    const int gr0 = (r0 >> 5) * H_D + (int)rank * 32 + (r0 & 31);
    const int gr1 = (r1 >> 5) * H_D + (int)rank * 32 + (r1 & 31);

    // ---- weights into registers: 2 rows x (k-slice) packed (k,k+1) ----
    unsigned long long W0[16], W1[16];
    if (isx) {
#pragma unroll
        for (int i = 0; i < XSL / 2; i++) {
            const int c = k0 + 2 * i;
            W0[i] = pack2(Wih[gr0 * KIN + c], Wih[gr0 * KIN + c + 1]);
            W1[i] = pack2(Wih[gr1 * KIN + c], Wih[gr1 * KIN + c + 1]);
        }
    } else {
#pragma unroll
        for (int i = 0; i < 16; i++) {
            const int c = k0 + 2 * i;
            W0[i] = pack2(Whh[gr0 * H_D + c], Whh[gr0 * H_D + c + 1]);
            W1[i] = pack2(Whh[gr1 * H_D + c], Whh[gr1 * H_D + c + 1]);
        }
    }

    // ---- epilogue identity (threads < 256 = x-warps) ----
    const int ob    = tid >> 5;                 // batch row 0..7
    const int oj    = tid & 31;
    const int jglob = (int)rank * 32 + oj;
    float bsum[4];
#pragma unroll
    for (int g = 0; g < 4; g++)
        bsum[g] = bih[g * H_D + jglob] + bhh[g * H_D + jglob];
    float c_state = 0.0f;
    float* out_p = out + ((size_t)b0 + ob) * H_D + jglob;

    // ---- staging identity (h-warps, tid >= 256): x(t+2) per thread ----
    // KIN=128: float4 each; KIN=64: float2 each. 256 threads cover 8*KIN.
    const int  si   = tid & 255;
    const int  srow = si >> 5;
    const int  scol = (KIN == 128) ? ((si & 31) << 2) : ((si & 31) << 1);
    const float* st_src =
        in + ((size_t)2 * B_SZ + b0 + srow) * KIN + scol;   // x(2)

    // ---- prologue: stage x(0), x(1); zero h(-1); x-dots for step 0 ----
    for (int i = tid; i < 8 * KIN; i += 512) {
        const int r = i / KIN, c = i % KIN;
        xs[0 * 8 * KIN + i] = in[((size_t)0 * B_SZ + b0 + r) * KIN + c];
        xs[1 * 8 * KIN + i] = in[((size_t)1 * B_SZ + b0 + r) * KIN + c];
    }
    for (int i = tid; i < 8 * H_D; i += 512) hs[i] = 0.0f;
    __syncthreads();

    if (isx)
        slab<NVX, KIN>(gbuf + (size_t)sl * 8 * 128, xs + k0, W0, W1, r0, r1);
    asm volatile("barrier.cluster.arrive.aligned;" ::: "memory");

    for (int t = 0; t < T_SEQ; t++) {
        const int cur = t & 1;
        const int nxt = cur ^ 1;
        const bool do_stage = (!isx) && (t + 2 < T_SEQ);

        // ---- pre-wait work: x-dots for t+1 (x-warps) hide the barrier;
        //      h-warps issue the x(t+2) LDG (DRAM latency hidden too).
        float4 pf;
        if (isx) {
            if (t + 1 < T_SEQ)
                slab<NVX, KIN>(gbuf + ((size_t)nxt * 8 + sl) * 8 * 128,
                               xs + nxt * 8 * KIN + k0, W0, W1, r0, r1);
        } else if (do_stage) {
            if (KIN == 128) pf = *(const float4*)st_src;
            else { const float2 p2 = *(const float2*)st_src;
                   pf.x = p2.x; pf.y = p2.y; }
        }

        // h(t-1) from all 4 ranks is published once the barrier releases
        asm volatile("barrier.cluster.wait.aligned;" ::: "memory");

        if (!isx) {
            // ---- h-dots for step t (the serial chain) ----
            slab<8, H_D>(gbuf + ((size_t)cur * 8 + sl) * 8 * 128,
                         hs + cur * 8 * H_D + k0, W0, W1, r0, r1);
            // stage x(t+2) into xs[cur] (consumed in iter t+1, after sync)
            if (do_stage) {
                float* d = xs + cur * 8 * KIN + srow * KIN + scol;
                if (KIN == 128) *(float4*)d = pf;
                else            *(float2*)d = make_float2(pf.x, pf.y);
                st_src += (size_t)B_SZ * KIN;
            }
        }

        __syncthreads();   // gbuf[cur] complete (x from iter t-1, h from t)

        if (tid < 256) {
            const float* gb = gbuf + (size_t)cur * 8 * 8 * 128;
            float gv[4];
#pragma unroll
            for (int g = 0; g < 4; g++) {
                float s = bsum[g];
#pragma unroll
                for (int q = 0; q < 8; q++)
                    s += gb[(q * 8 + ob) * 128 + g * 32 + oj];
                gv[g] = s;
            }
            const float ig = fsig(gv[0]);
            const float fg = fsig(gv[1]);
            const float gg = ftanh(gv[2]);
            const float og = fsig(gv[3]);
            c_state = fg * c_state + ig * gg;
            const float h = og * ftanh(c_state);

            if (t + 1 < T_SEQ) {
                float* hp = hs + nxt * 8 * H_D + ob * H_D + jglob;
                *hp = h;
                const uint32_t laddr = (uint32_t)__cvta_generic_to_shared(hp);
#pragma unroll
                for (int pr = 0; pr < 4; pr++) {
                    if (pr != (int)rank) {
                        asm volatile(
                            "{ .reg .b32 ra;\n\t"
                            "  mapa.shared::cluster.u32 ra, %0, %1;\n\t"
                            "  st.shared::cluster.f32 [ra], %2; }"
                            :: "r"(laddr), "r"(pr), "f"(h) : "memory");
                    }
                }
            }
            *out_p = h;
            out_p += (size_t)B_SZ * H_D;
        }

        if (t + 1 < T_SEQ)
            asm volatile("barrier.cluster.arrive.aligned;" ::: "memory");
    }
}

// ============================================================================
// kernel_launch: 5 sequential layer kernels (graph-capturable, no allocs)
// ============================================================================
static const int SMEM64  = (2 * 8 * 8 * 128 + 2 * 8 * 64  + 2 * 8 * 128) * 4;
static const int SMEM128 = (2 * 8 * 8 * 128 + 2 * 8 * 128 + 2 * 8 * 128) * 4;

extern "C" void kernel_launch(void* const* d_in, const int* in_sizes, int n_in,
                              void* d_out, int out_size) {
    const float* x     = (const float*)d_in[0];   // [512,256,64]
    const float* Wih0  = (const float*)d_in[1];   // [512,64]
    const float* Wrest = (const float*)d_in[2];   // [4,512,128]
    const float* Whh   = (const float*)d_in[3];   // [5,512,128]
    const float* bih   = (const float*)d_in[4];   // [5,512]
    const float* bhh   = (const float*)d_in[5];   // [5,512]
    float* out = (float*)d_out;                   // [512,256,128]

    float *bufA = nullptr, *bufB = nullptr;
    cudaGetSymbolAddress((void**)&bufA, g_bufA);
    cudaGetSymbolAddress((void**)&bufB, g_bufB);

    cudaFuncSetAttribute(lstm_layer<IN_D>,
        cudaFuncAttributeMaxDynamicSharedMemorySize, SMEM64);
    cudaFuncSetAttribute(lstm_layer<H_D>,
        cudaFuncAttributeMaxDynamicSharedMemorySize, SMEM128);

    const dim3 grid(128), block(512);

    lstm_layer<IN_D><<<grid, block, SMEM64>>>(
        x, bufA, Wih0, Whh + 0 * G4 * H_D, bih + 0 * G4, bhh + 0 * G4);
    lstm_layer<H_D><<<grid, block, SMEM128>>>(
        bufA, bufB, Wrest + 0 * G4 * H_D, Whh + 1 * G4 * H_D,
        bih + 1 * G4, bhh + 1 * G4);
    lstm_layer<H_D><<<grid, block, SMEM128>>>(
        bufB, bufA, Wrest + 1 * G4 * H_D, Whh + 2 * G4 * H_D,
        bih + 2 * G4, bhh + 2 * G4);
    lstm_layer<H_D><<<grid, block, SMEM128>>>(
        bufA, bufB, Wrest + 2 * G4 * H_D, Whh + 3 * G4 * H_D,
        bih + 3 * G4, bhh + 3 * G4);
    lstm_layer<H_D><<<grid, block, SMEM128>>>(
        bufB, out, Wrest + 3 * G4 * H_D, Whh + 4 * G4 * H_D,
        bih + 4 * G4, bhh + 4 * G4);
}